// round 14
// baseline (speedup 1.0000x reference)
#include <cuda_runtime.h>
#include <math.h>

#define FULLMASK 0xffffffffu
#define NF   216
#define TLEN 2048
#define NTF  341   // fwd triples: t = 2..1024
#define NTB  340   // bwd triples: t = 2044..1025

// dynamic smem layout (bytes)
#define OFF_B     0                      // 216*32*4 = 27648 (fp32 emission table)
#define OFF_FQ1   27648                  // uint2[216*25] = 43200 (sFlat aliases here)
#define OFF_FQ2   70848                  // 43200
#define OFF_BQ1   114048                 // 43200
#define OFF_BQ2   157248                 // 43200 -> 200448
#define OFF_TRF   200448                 // 4*344*8 = 11008
#define OFF_TRB   211456                 // 11008 -> 222464
#define OFF_A     222464                 // 2512
#define OFF_I     224976                 // 128
#define OFF_RED   225104                 // 512
#define OFF_SUCC  225616                 // 512
#define SMEM_TOTAL 226128

// ---------------- constant tables ----------------
__constant__ __align__(16) int c_srcTab[32 * 4] = {
    0,0,0,0,     0,1,1,1,     1,2,2,2,     2,3,3,3,
    3,16,4,4,    4,5,5,5,     5,6,6,6,     6,19,3,7,
    7,8,8,8,     8,9,9,9,     9,22,3,6,    10,11,11,11,
    11,12,12,12, 12,13,13,13, 3,16,14,14,  14,15,15,15,
    15,16,16,16, 6,19,17,17,  17,18,18,18, 18,19,19,19,
    9,22,20,20,  20,21,21,21, 21,22,22,22, 13,23,23,23,
    23,24,24,24, 25,25,25,25, 26,26,26,26, 27,27,27,27,
    28,28,28,28, 29,29,29,29, 30,30,30,30, 31,31,31,31
};
__constant__ int c_deg[32] = {1,1,1,1,2,1,1,3,1,1,4,1,1,2,2,1,1,2,1,1,2,1,1,2,2,0,0,0,0,0,0,0};

__constant__ int c_pred[25][4] = {
    {0,0,0,0},{0,0,0,0},{1,0,0,0},{2,0,0,0},{3,16,0,0},{4,0,0,0},{5,0,0,0},
    {6,19,3,0},{7,0,0,0},{8,0,0,0},{9,22,3,6},{10,0,0,0},{11,0,0,0},{12,13,0,0},
    {3,16,0,0},{14,0,0,0},{15,0,0,0},{6,19,0,0},{17,0,0,0},{18,0,0,0},
    {9,22,0,0},{20,0,0,0},{21,0,0,0},{13,23,0,0},{23,24,0,0}
};
__constant__ int c_pcnt[25] = {1,1,1,1,2,1,1,3,1,1,4,1,1,2,2,1,1,2,1,1,2,1,1,2,2};

__constant__ int c_adds[29][7] = {
    { 0, 10,10,10, 0,1,    0},
    { 1, 10,10, 0, 0,1,   84},
    { 2, 10, 0, 3, 0,1,  105},
    { 3,  0, 3, 2, 0,0,    0},
    { 4,  3, 2,10, 0,1,  111},
    { 5,  2,10,10, 0,1,  123},
    { 6, 10,10,10, 0,1,  159},
    { 7, 10,10,10, 0,1,  243},
    { 8, 10,10,10, 0,1,  327},
    { 9, 10,10,10, 0,1,  411},
    {10, 10,10, 3, 2,1,  495},
    {11, 10, 3, 0, 2,1,  511},
    {11, 10, 3, 2, 2,1,  515},
    {12,  3, 0, 0, 2,0,    0},
    {12,  3, 0, 2, 2,0,    0},
    {12,  3, 2, 0, 2,0,    0},
    {13, 10,10,10, 2,1,  519},
    {14, 10,10,10, 0,1,  583},
    {15, 10,10,10, 0,1,  667},
    {16, 10,10,10, 0,1,  751},
    {17, 10,10,10, 0,1,  835},
    {18, 10,10,10, 0,1,  919},
    {19, 10,10,10, 0,1, 1003},
    {20, 10,10,10, 0,1, 1087},
    {21, 10,10,10, 0,1, 1171},
    {22, 10,10,10, 0,1, 1255},
    {23, 10,10, 5, 2,1, 1339},
    {23, 10, 5, 5, 2,1, 1355},
    {24,  5, 5, 5, 2,0,    0}
};

// ---------------- helpers ----------------
__device__ __forceinline__ int codeList(int ch, int* o) {
    if (ch == 10) { o[0]=0; o[1]=1; o[2]=2; o[3]=3; return 4; }
    o[0] = ch; return 1;
}

__device__ void addB(float* shB, const float* w,
                     int state, int e0, int e1, int e2,
                     int xp, int trainable, int k)
{
    int a0[6], a1[6], a2[6];
    int n0 = codeList(e0, a0);
    int n1 = codeList(e1, a1);
    int n2 = codeList(e2, a2);
    if (xp == 0) { a0[n0++] = 4; a1[n1++] = 4; }
    int t = 0;
    for (int i0 = 0; i0 < n0; i0++) { int c0 = a0[i0];
        for (int i1 = 0; i1 < n1; i1++) { int c1 = a1[i1];
            if (c0 != 4 && c1 == 4) continue;
            for (int i2 = 0; i2 < n2; i2++) { int c2 = a2[i2];
                shB[((c0*36 + c1*6 + c2) << 5) + state] = trainable ? w[k + t] : 1.0f;
                t++;
            }
        }
    }
}

__device__ __forceinline__ unsigned bf16rn(float v) {
    unsigned b = __float_as_uint(v);
    return (b + 0x7fffu + ((b >> 16) & 1u)) >> 16;
}

// ---------------- fused kernel: per-warp forward+backward dual chain ----------------
__global__ __launch_bounds__(128, 1)
void hmm_fb2(const float* __restrict__ tw,
             const float* __restrict__ ew,
             const float* __restrict__ iw,
             const int* __restrict__ tokens,
             float* __restrict__ out, int rows)
{
    extern __shared__ char dyn[];
    float*  shB   = (float*) (dyn + OFF_B);
    uint2*  fQ1   = (uint2*) (dyn + OFF_FQ1);
    uint2*  fQ2   = (uint2*) (dyn + OFF_FQ2);
    uint2*  bQ1   = (uint2*) (dyn + OFF_BQ1);
    uint2*  bQ2   = (uint2*) (dyn + OFF_BQ2);
    short*  sFlat = (short*) (dyn + OFF_FQ1);   // alias, dead before fQ1 built
    short4* sTrF  = (short4*)(dyn + OFF_TRF);
    short4* sTrB  = (short4*)(dyn + OFF_TRB);
    float*  sA    = (float*) (dyn + OFF_A);
    float*  sI    = (float*) (dyn + OFF_I);
    float*  sRed  = (float*) (dyn + OFF_RED);
    int*    sSucc = (int*)   (dyn + OFF_SUCC);
    int*    sScnt = (int*)   (dyn + OFF_SUCC + 400);

    const int tid  = threadIdx.x;
    const int lane = tid & 31;
    const int wq   = tid >> 5;      // 0..3
    const int row  = blockIdx.x * 4 + wq;

    // ---- P1: init ----
    for (int i = tid; i < NF*32; i += 128) shB[i] = ((i & 31) < 25) ? -1e30f : 0.f;
    for (int i = tid; i < 625;   i += 128) sA[i] = -1e30f;
    __syncthreads();

    // ---- P2: logits + I + flats ----
    if (tid < 29) {
        const int* d = c_adds[tid];
        addB(shB, ew, d[0], d[1], d[2], d[3], d[4], d[5], d[6]);
    }
    if (tid == 32) {
        float w0=tw[0],w1=tw[1],w2=tw[2],w3=tw[3],w4=tw[4];
        float w5=tw[5],w6=tw[6],w7=tw[7],w8=tw[8],w9=tw[9];
        sA[0*25+0]=1.f-w0; sA[0*25+1]=w0;
        sA[1*25+2]=1.f;    sA[2*25+3]=1.f;
        sA[3*25+4]=w1;     sA[6*25+7]=w2;
        sA[4*25+5]=1.f;    sA[7*25+8]=1.f;
        sA[5*25+6]=1.f;    sA[8*25+9]=1.f;
        sA[3*25+14]=w3;    sA[6*25+17]=w4;   sA[9*25+20]=w5;
        sA[9*25+10]=1.f-w5;
        sA[14*25+15]=1.f;  sA[17*25+18]=1.f; sA[20*25+21]=1.f;
        sA[15*25+16]=1.f;  sA[18*25+19]=1.f; sA[21*25+22]=1.f;
        sA[16*25+4]=w6;    sA[19*25+7]=w7;   sA[22*25+10]=w8;
        sA[16*25+14]=1.f-w6; sA[19*25+17]=1.f-w7; sA[22*25+20]=1.f-w8;
        sA[3*25+7]=1.f - w9*w9;
        sA[3*25+10]=1.f - w9*w9*w9;
        sA[6*25+10]=1.f - w9*w9;
        sA[10*25+11]=1.f; sA[11*25+12]=1.f; sA[12*25+13]=1.f;
        sA[13*25+13]=1.f; sA[13*25+23]=1.f;
        sA[23*25+23]=1.f; sA[23*25+24]=1.f; sA[24*25+24]=1.f;
    }
    if (tid == 64) {
        float mx = -1e30f;
        for (int i = 0; i < 9; i++) mx = fmaxf(mx, iw[i]);
        float v[9], sum = 0.f;
        for (int i = 0; i < 9; i++) { v[i] = expf(iw[i]-mx); sum += v[i]; }
        for (int i = 0; i < 9; i++) sI[i] = v[i] / sum;
        for (int i = 9; i < 32; i++) sI[i] = 0.f;
    }
    // flats: each warp computes its full row
    short* fl = sFlat + wq * TLEN;
    const int* tok = tokens + (size_t)row * TLEN;
    if (row < rows) {
        int c1 = 4, c2 = 4;
        for (int t0 = 0; t0 < TLEN; t0 += 32) {
            int tcv = tok[t0 + lane];
            int t1v = __shfl_up_sync(FULLMASK, tcv, 1);
            int t2v = __shfl_up_sync(FULLMASK, tcv, 2);
            if (lane == 0) { t1v = c1; t2v = c2; }
            if (lane == 1) { t2v = c1; }
            fl[t0 + lane] = (short)(t2v*36 + t1v*6 + tcv);
            c2 = __shfl_sync(FULLMASK, tcv, 30);
            c1 = __shfl_sync(FULLMASK, tcv, 31);
        }
    }
    __syncthreads();

    // ---- P3: trips + A softmax + succ lists ----
    short4* trF = sTrF + wq * 344;
    short4* trB = sTrB + wq * 344;
    int flat0 = 168, flat1 = 144, f45 = 0, f46 = 0, f47 = 0;
    if (row < rows) {
        for (int i = lane; i < NTF; i += 32) {
            int b = 2 + 3*i;
            trF[i] = make_short4(fl[b], fl[b+1], fl[b+2], 0);
        }
        for (int q = lane; q < NTB; q += 32) {
            int t = 2042 - 3*q;
            trB[q] = make_short4(fl[t], fl[t+1], fl[t+2], 0);
        }
        flat0 = fl[0]; flat1 = fl[1];
        f45 = fl[2045]; f46 = fl[2046]; f47 = fl[2047];
    }
    if (tid < 25) {   // A row softmax
        float mx = -1e30f;
        for (int j = 0; j < 25; j++) mx = fmaxf(mx, sA[tid*25+j]);
        float s = 0.f;
        for (int j = 0; j < 25; j++) { float v = expf(sA[tid*25+j]-mx); sA[tid*25+j]=v; s+=v; }
        float inv = 1.f / s;
        for (int j = 0; j < 25; j++) sA[tid*25+j] *= inv;
    }
    if (tid < 25) {   // successor lists (targets <= 22; 23/24 pruned)
        int cnt = 0;
        for (int j = 0; j < 23; j++)
            for (int p = 0; p < c_pcnt[j]; p++)
                if (c_pred[j][p] == tid && cnt < 4) sSucc[tid*4 + cnt++] = j;
        for (int p = cnt; p < 4; p++) sSucc[tid*4 + p] = tid;
        sScnt[tid] = cnt;
    }
    __syncthreads();

    // ---- P4: B column softmax, 4 warps x 54 flats ----
    {
        const int s  = lane;
        const int f0 = wq * 54, f1 = f0 + 54;
        float mx = -1e30f;
        for (int f = f0; f < f1; f++) mx = fmaxf(mx, shB[(f<<5)+s]);
        sRed[wq*32 + s] = mx;
        __syncthreads();
        mx = fmaxf(fmaxf(sRed[s], sRed[32+s]), fmaxf(sRed[64+s], sRed[96+s]));
        float sum = 0.f;
        for (int f = f0; f < f1; f++) {
            float v = __expf(shB[(f<<5)+s] - mx);
            shB[(f<<5)+s] = v; sum += v;
        }
        __syncthreads();
        sRed[wq*32 + s] = sum;
        __syncthreads();
        float tot = (sRed[s] + sRed[32+s]) + (sRed[64+s] + sRed[96+s]);
        float inv = 1.f / tot;
        for (int f = f0; f < f1; f++) shB[(f<<5)+s] *= inv;
    }
    __syncthreads();

    // ---- P5: path constants + tables ----
    // forward 3-step paths (s -> k1 -> k2 -> lane); 23/24 pruned (emission 0)
    int   ps[4] = {0,0,0,0}, j1[4] = {0,0,0,0}, j2[4] = {0,0,0,0};
    float pcc[4] = {0.f,0.f,0.f,0.f};
    if (lane < 25) {
        int cnt = 0;
        for (int a2 = 0; a2 < c_pcnt[lane]; a2++) {
            int k2 = c_pred[lane][a2];
            if (k2 >= 23) continue;
            for (int a1 = 0; a1 < c_pcnt[k2]; a1++) {
                int k1 = c_pred[k2][a1];
                if (k1 >= 23) continue;
                for (int a0 = 0; a0 < c_pcnt[k1]; a0++) {
                    int s = c_pred[k1][a0];
                    if (cnt < 4) {
                        ps[cnt]=s; j1[cnt]=k1; j2[cnt]=k2;
                        pcc[cnt] = sA[s*25+k1]*sA[k1*25+k2]*sA[k2*25+lane]*8388608.0f;
                        cnt++;
                    }
                }
            }
        }
    }
    const int S0 = ps[0], S1 = ps[1], S2 = ps[2], S3 = ps[3];

    // backward 3-step paths (lane -> u1 -> u2 -> u3)
    int   bu1[4] = {0,0,0,0}, bu2[4] = {0,0,0,0}, bu3[4];
    bu3[0]=lane; bu3[1]=lane; bu3[2]=lane; bu3[3]=lane;
    float bcc[4] = {0.f,0.f,0.f,0.f};
    if (lane < 25) {
        int cnt = 0;
        int n0s = sScnt[lane];
        for (int ai = 0; ai < n0s; ai++) {
            int a_ = sSucc[lane*4+ai];
            for (int bi = 0; bi < sScnt[a_]; bi++) {
                int b_ = sSucc[a_*4+bi];
                for (int ci = 0; ci < sScnt[b_]; ci++) {
                    int c_ = sSucc[b_*4+ci];
                    if (cnt < 4) {
                        bu1[cnt]=a_; bu2[cnt]=b_; bu3[cnt]=c_;
                        bcc[cnt] = sA[lane*25+a_]*sA[a_*25+b_]*sA[b_*25+c_]*8388608.0f;
                        cnt++;
                    }
                }
            }
        }
    }
    const int D0 = bu3[0], D1 = bu3[1], D2 = bu3[2], D3 = bu3[3];

    // 1-step in-edge table (fwd t=1 and combine)
    const int u0 = c_srcTab[lane*4+0], u1 = c_srcTab[lane*4+1];
    const int u2 = c_srcTab[lane*4+2], u3 = c_srcTab[lane*4+3];
    const int dg = c_deg[lane];
    float v0 = (lane < 25 && dg > 0) ? sA[u0*25 + lane] : 0.f;
    float v1 = (lane < 25 && dg > 1) ? sA[u1*25 + lane] : 0.f;
    float v2 = (lane < 25 && dg > 2) ? sA[u2*25 + lane] : 0.f;
    float v3 = (lane < 25 && dg > 3) ? sA[u3*25 + lane] : 0.f;

    // 1-step successor table (bwd singles)
    int   su[4]; su[0]=lane; su[1]=lane; su[2]=lane; su[3]=lane;
    float wv[4] = {0.f,0.f,0.f,0.f};
    if (lane < 25) {
        int n = sScnt[lane];
        for (int p = 0; p < n; p++) { su[p] = sSucc[lane*4+p]; wv[p] = sA[lane*25+su[p]]; }
    }

    // build the 4 bf16 tables (stride 25)
    if (lane < 25) {
        for (int f = wq * 54; f < wq * 54 + 54; f++) {
            int fo = f << 5;
            uint2 q;
            q.x = bf16rn(shB[fo+j1[0]]) | (bf16rn(shB[fo+j1[1]]) << 16);
            q.y = bf16rn(shB[fo+j1[2]]) | (bf16rn(shB[fo+j1[3]]) << 16);
            fQ1[f*25+lane] = q;
            q.x = bf16rn(pcc[0]*shB[fo+j2[0]]) | (bf16rn(pcc[1]*shB[fo+j2[1]]) << 16);
            q.y = bf16rn(pcc[2]*shB[fo+j2[2]]) | (bf16rn(pcc[3]*shB[fo+j2[3]]) << 16);
            fQ2[f*25+lane] = q;
            q.x = bf16rn(shB[fo+bu1[0]]) | (bf16rn(shB[fo+bu1[1]]) << 16);
            q.y = bf16rn(shB[fo+bu1[2]]) | (bf16rn(shB[fo+bu1[3]]) << 16);
            bQ1[f*25+lane] = q;
            q.x = bf16rn(bcc[0]*shB[fo+bu2[0]]) | (bf16rn(bcc[1]*shB[fo+bu2[1]]) << 16);
            q.y = bf16rn(bcc[2]*shB[fo+bu2[2]]) | (bf16rn(bcc[3]*shB[fo+bu2[3]]) << 16);
            bQ2[f*25+lane] = q;
        }
    }
    __syncthreads();

    if (row >= rows) return;

    // ================= main: dual chain in one warp =================
    // forward init: t0, t1
    float a = sI[lane] * shB[(flat0 << 5) + lane];
    {
        float e = shB[(flat1 << 5) + lane];
        float x0 = __shfl_sync(FULLMASK, a, u0);
        float x1 = __shfl_sync(FULLMASK, a, u1);
        float x2 = __shfl_sync(FULLMASK, a, u2);
        float x3 = __shfl_sync(FULLMASK, a, u3);
        a = (fmaf(x0, v0, x1*v1) + fmaf(x2, v2, x3*v3)) * e;
    }
    // backward init: t=2047, singles 2046, 2045
    float g = shB[(f47 << 5) + lane];
    {
        int fs[2]; fs[0] = f46; fs[1] = f45;
        for (int k = 0; k < 2; k++) {
            float e = shB[(fs[k] << 5) + lane];
            float x0 = __shfl_sync(FULLMASK, g, su[0]);
            float x1 = __shfl_sync(FULLMASK, g, su[1]);
            float x2 = __shfl_sync(FULLMASK, g, su[2]);
            float x3 = __shfl_sync(FULLMASK, g, su[3]);
            g = e * (fmaf(x1, wv[1], x0*wv[0]) + fmaf(x3, wv[3], x2*wv[2]));
        }
    }

    int eF = 0, eB = 0;
    float scF = 1.f, scB = 1.f;
    int pendF = 0, pendB = 0;

#define TRIPF(I, MODE)                                                        \
    {                                                                         \
        short4 tf = trF[(I)];                                                 \
        uint2 qa = fQ1[(int)tf.x * 25 + lane];                                \
        uint2 qb = fQ2[(int)tf.y * 25 + lane];                                \
        float e  = shB[(((int)tf.z) << 5) + lane];                            \
        float w0_ = __uint_as_float(qa.x << 16)         * __uint_as_float(qb.x << 16)         * e; \
        float w1_ = __uint_as_float(qa.x & 0xffff0000u) * __uint_as_float(qb.x & 0xffff0000u) * e; \
        float w2_ = __uint_as_float(qa.y << 16)         * __uint_as_float(qb.y << 16)         * e; \
        float w3_ = __uint_as_float(qa.y & 0xffff0000u) * __uint_as_float(qb.y & 0xffff0000u) * e; \
        float x0 = __shfl_sync(FULLMASK, a, S0);                              \
        float x1 = __shfl_sync(FULLMASK, a, S1);                              \
        float x2 = __shfl_sync(FULLMASK, a, S2);                              \
        float x3 = __shfl_sync(FULLMASK, a, S3);                              \
        a = fmaf(x1, w1_, x0*w0_) + fmaf(x3, w3_, x2*w2_);                    \
        if ((MODE) == 1) {                                                    \
            int m = __reduce_max_sync(FULLMASK, (__float_as_int(a) >> 23) & 255); \
            scF = __int_as_float((254 - m) << 23);                            \
            pendF = m - 127;                                                  \
        }                                                                     \
        if ((MODE) == 2) { a *= scF; eF += pendF; }                           \
    }

#define TRIPB(I, MODE)                                                        \
    {                                                                         \
        short4 tf = trB[(I)];                                                 \
        float e  = shB[(((int)tf.x) << 5) + lane];                            \
        uint2 qa = bQ1[(int)tf.y * 25 + lane];                                \
        uint2 qb = bQ2[(int)tf.z * 25 + lane];                                \
        float w0_ = __uint_as_float(qa.x << 16)         * __uint_as_float(qb.x << 16)         * e; \
        float w1_ = __uint_as_float(qa.x & 0xffff0000u) * __uint_as_float(qb.x & 0xffff0000u) * e; \
        float w2_ = __uint_as_float(qa.y << 16)         * __uint_as_float(qb.y << 16)         * e; \
        float w3_ = __uint_as_float(qa.y & 0xffff0000u) * __uint_as_float(qb.y & 0xffff0000u) * e; \
        float x0 = __shfl_sync(FULLMASK, g, D0);                              \
        float x1 = __shfl_sync(FULLMASK, g, D1);                              \
        float x2 = __shfl_sync(FULLMASK, g, D2);                              \
        float x3 = __shfl_sync(FULLMASK, g, D3);                              \
        g = fmaf(x1, w1_, x0*w0_) + fmaf(x3, w3_, x2*w2_);                    \
        if ((MODE) == 1) {                                                    \
            int m = __reduce_max_sync(FULLMASK, (__float_as_int(g) >> 23) & 255); \
            scB = __int_as_float((254 - m) << 23);                            \
            pendB = m - 127;                                                  \
        }                                                                     \
        if ((MODE) == 2) { g *= scB; eB += pendB; }                           \
    }

    // head: fwd trips 0..4 (measure@2, apply@4), bwd trips 0..3 (measure@1, apply@3)
    TRIPF(0,0) TRIPB(0,0)
    TRIPF(1,0) TRIPB(1,1)
    TRIPF(2,1) TRIPB(2,0)
    TRIPF(3,0) TRIPB(3,2)
    TRIPF(4,2)

    // main: 42 blocks of 8 dual iters (fwd 5..340, bwd 4..339)
#define STAGEF(i)                                                             \
    {                                                                         \
        short4 tf = trF[ibf + (i)];                                           \
        uint2 qa = fQ1[(int)tf.x * 25 + lane];                                \
        uint2 qb = fQ2[(int)tf.y * 25 + lane];                                \
        float e  = shB[(((int)tf.z) << 5) + lane];                            \
        WF[(i)][0] = __uint_as_float(qa.x << 16)         * __uint_as_float(qb.x << 16)         * e; \
        WF[(i)][1] = __uint_as_float(qa.x & 0xffff0000u) * __uint_as_float(qb.x & 0xffff0000u) * e; \
        WF[(i)][2] = __uint_as_float(qa.y << 16)         * __uint_as_float(qb.y << 16)         * e; \
        WF[(i)][3] = __uint_as_float(qa.y & 0xffff0000u) * __uint_as_float(qb.y & 0xffff0000u) * e; \
    }
#define STAGEB(i)                                                             \
    {                                                                         \
        short4 tf = trB[ibb + (i)];                                           \
        float e  = shB[(((int)tf.x) << 5) + lane];                            \
        uint2 qa = bQ1[(int)tf.y * 25 + lane];                                \
        uint2 qb = bQ2[(int)tf.z * 25 + lane];                                \
        WB[(i)][0] = __uint_as_float(qa.x << 16)         * __uint_as_float(qb.x << 16)         * e; \
        WB[(i)][1] = __uint_as_float(qa.x & 0xffff0000u) * __uint_as_float(qb.x & 0xffff0000u) * e; \
        WB[(i)][2] = __uint_as_float(qa.y << 16)         * __uint_as_float(qb.y << 16)         * e; \
        WB[(i)][3] = __uint_as_float(qa.y & 0xffff0000u) * __uint_as_float(qb.y & 0xffff0000u) * e; \
    }

    for (int ibf = 5, ibb = 4; ibf <= 333; ibf += 8, ibb += 8) {
        float WF[8][4], WB[8][4];
        STAGEF(0) STAGEB(0) STAGEF(1) STAGEB(1)
        #pragma unroll
        for (int i = 0; i < 8; i++) {
            if (i < 6) { STAGEF(i+2) STAGEB(i+2) }
            float xa0 = __shfl_sync(FULLMASK, a, S0);
            float xa1 = __shfl_sync(FULLMASK, a, S1);
            float xa2 = __shfl_sync(FULLMASK, a, S2);
            float xa3 = __shfl_sync(FULLMASK, a, S3);
            float xb0 = __shfl_sync(FULLMASK, g, D0);
            float xb1 = __shfl_sync(FULLMASK, g, D1);
            float xb2 = __shfl_sync(FULLMASK, g, D2);
            float xb3 = __shfl_sync(FULLMASK, g, D3);
            a = fmaf(xa1, WF[i][1], xa0*WF[i][0]) + fmaf(xa3, WF[i][3], xa2*WF[i][2]);
            g = fmaf(xb1, WB[i][1], xb0*WB[i][0]) + fmaf(xb3, WB[i][3], xb2*WB[i][2]);
            if (i == 5) {
                int mF = __reduce_max_sync(FULLMASK, (__float_as_int(a) >> 23) & 255);
                int mB = __reduce_max_sync(FULLMASK, (__float_as_int(g) >> 23) & 255);
                scF = __int_as_float((254 - mF) << 23); pendF = mF - 127;
                scB = __int_as_float((254 - mB) << 23); pendB = mB - 127;
            }
            if (i == 7) {
                a *= scF; eF += pendF;
                g *= scB; eB += pendB;
            }
        }
    }
#undef STAGEF
#undef STAGEB
#undef TRIPF
#undef TRIPB

    // ---- combine: P = (alpha_1024 A) . gamma_1025 ----
    {
        float x0 = __shfl_sync(FULLMASK, a, u0);
        float x1 = __shfl_sync(FULLMASK, a, u1);
        float x2 = __shfl_sync(FULLMASK, a, u2);
        float x3 = __shfl_sync(FULLMASK, a, u3);
        float z = fmaf(x0, v0, x1*v1) + fmaf(x2, v2, x3*v3);
        float P = z * g;
        #pragma unroll
        for (int o = 16; o; o >>= 1) P += __shfl_xor_sync(FULLMASK, P, o);
        if (lane == 0)
            out[row] = logf(P) + 0.6931471805599453f * (float)(eF + eB - 15663);
    }
}

// ---------------- entry point ----------------
extern "C" void kernel_launch(void* const* d_in, const int* in_sizes, int n_in,
                              void* d_out, int out_size)
{
    const float* tw     = (const float*)d_in[0];
    const float* ew     = (const float*)d_in[1];
    const float* iw     = (const float*)d_in[2];
    const int*   tokens = (const int*)  d_in[3];
    float*       out    = (float*)d_out;

    int rows = in_sizes[3] / TLEN;

    cudaFuncSetAttribute(hmm_fb2,
                         cudaFuncAttributeMaxDynamicSharedMemorySize,
                         SMEM_TOTAL);
    hmm_fb2<<<(rows + 3) / 4, 128, SMEM_TOTAL>>>(tw, ew, iw, tokens, out, rows);
}

// round 15
// speedup vs baseline: 1.2699x; 1.2699x over previous
#include <cuda_runtime.h>
#include <cuda_bf16.h>
#include <math.h>

#define FULLMASK 0xffffffffu
#define NF   216
#define TLEN 2048
#define NTRIP 682          // triples covering t = 2 .. 2047

// dynamic smem layout (bytes)
#define OFF_B     0                          // 216*32*4 = 27648
#define OFF_Q1B   27648                      // uint2[216*32] = 55296 (sFlat aliases here)
#define OFF_Q2B   82944                      // 55296 -> 138240
#define OFF_TRIP  138240                     // 4*684*8 = 21888 -> 160128
#define OFF_A     160128                     // 2512
#define OFF_I     162640                     // 128
#define OFF_RED   162768                     // 512
#define SMEM_TOTAL 163280

// ---------------- constant tables ----------------
__constant__ __align__(16) int c_srcTab[32 * 4] = {
    0,0,0,0,     0,1,1,1,     1,2,2,2,     2,3,3,3,
    3,16,4,4,    4,5,5,5,     5,6,6,6,     6,19,3,7,
    7,8,8,8,     8,9,9,9,     9,22,3,6,    10,11,11,11,
    11,12,12,12, 12,13,13,13, 3,16,14,14,  14,15,15,15,
    15,16,16,16, 6,19,17,17,  17,18,18,18, 18,19,19,19,
    9,22,20,20,  20,21,21,21, 21,22,22,22, 13,23,23,23,
    23,24,24,24, 25,25,25,25, 26,26,26,26, 27,27,27,27,
    28,28,28,28, 29,29,29,29, 30,30,30,30, 31,31,31,31
};
__constant__ int c_deg[32] = {1,1,1,1,2,1,1,3,1,1,4,1,1,2,2,1,1,2,1,1,2,1,1,2,2,0,0,0,0,0,0,0};

__constant__ int c_pred[25][4] = {
    {0,0,0,0},{0,0,0,0},{1,0,0,0},{2,0,0,0},{3,16,0,0},{4,0,0,0},{5,0,0,0},
    {6,19,3,0},{7,0,0,0},{8,0,0,0},{9,22,3,6},{10,0,0,0},{11,0,0,0},{12,13,0,0},
    {3,16,0,0},{14,0,0,0},{15,0,0,0},{6,19,0,0},{17,0,0,0},{18,0,0,0},
    {9,22,0,0},{20,0,0,0},{21,0,0,0},{13,23,0,0},{23,24,0,0}
};
__constant__ int c_pcnt[25] = {1,1,1,1,2,1,1,3,1,1,4,1,1,2,2,1,1,2,1,1,2,1,1,2,2};

__constant__ int c_adds[29][7] = {
    { 0, 10,10,10, 0,1,    0},
    { 1, 10,10, 0, 0,1,   84},
    { 2, 10, 0, 3, 0,1,  105},
    { 3,  0, 3, 2, 0,0,    0},
    { 4,  3, 2,10, 0,1,  111},
    { 5,  2,10,10, 0,1,  123},
    { 6, 10,10,10, 0,1,  159},
    { 7, 10,10,10, 0,1,  243},
    { 8, 10,10,10, 0,1,  327},
    { 9, 10,10,10, 0,1,  411},
    {10, 10,10, 3, 2,1,  495},
    {11, 10, 3, 0, 2,1,  511},
    {11, 10, 3, 2, 2,1,  515},
    {12,  3, 0, 0, 2,0,    0},
    {12,  3, 0, 2, 2,0,    0},
    {12,  3, 2, 0, 2,0,    0},
    {13, 10,10,10, 2,1,  519},
    {14, 10,10,10, 0,1,  583},
    {15, 10,10,10, 0,1,  667},
    {16, 10,10,10, 0,1,  751},
    {17, 10,10,10, 0,1,  835},
    {18, 10,10,10, 0,1,  919},
    {19, 10,10,10, 0,1, 1003},
    {20, 10,10,10, 0,1, 1087},
    {21, 10,10,10, 0,1, 1171},
    {22, 10,10,10, 0,1, 1255},
    {23, 10,10, 5, 2,1, 1339},
    {23, 10, 5, 5, 2,1, 1355},
    {24,  5, 5, 5, 2,0,    0}
};

// ---------------- helpers ----------------
__device__ __forceinline__ int codeList(int ch, int* o) {
    if (ch == 10) { o[0]=0; o[1]=1; o[2]=2; o[3]=3; return 4; }
    o[0] = ch; return 1;
}

__device__ void addB(float* shB, const float* w,
                     int state, int e0, int e1, int e2,
                     int xp, int trainable, int k)
{
    int a0[6], a1[6], a2[6];
    int n0 = codeList(e0, a0);
    int n1 = codeList(e1, a1);
    int n2 = codeList(e2, a2);
    if (xp == 0) { a0[n0++] = 4; a1[n1++] = 4; }
    int t = 0;
    for (int i0 = 0; i0 < n0; i0++) { int c0 = a0[i0];
        for (int i1 = 0; i1 < n1; i1++) { int c1 = a1[i1];
            if (c0 != 4 && c1 == 4) continue;
            for (int i2 = 0; i2 < n2; i2++) { int c2 = a2[i2];
                shB[((c0*36 + c1*6 + c2) << 5) + state] = trainable ? w[k + t] : 1.0f;
                t++;
            }
        }
    }
}

__device__ __forceinline__ unsigned bf16rn(float v) {
    unsigned b = __float_as_uint(v);
    return (b + 0x7fffu + ((b >> 16) & 1u)) >> 16;
}

// packed bf16x2 multiply, result unpacked to 2 fp32
__device__ __forceinline__ float2 bfmul2(unsigned a, unsigned b) {
    __nv_bfloat162 x = *reinterpret_cast<__nv_bfloat162*>(&a);
    __nv_bfloat162 y = *reinterpret_cast<__nv_bfloat162*>(&b);
    __nv_bfloat162 r = __hmul2(x, y);
    unsigned u = *reinterpret_cast<unsigned*>(&r);
    return make_float2(__uint_as_float(u << 16), __uint_as_float(u & 0xffff0000u));
}

// ---------------- fused kernel: 3 steps/iter ----------------
__global__ __launch_bounds__(128, 1)
void hmm_fused(const float* __restrict__ tw,
               const float* __restrict__ ew,
               const float* __restrict__ iw,
               const int* __restrict__ tokens,
               float* __restrict__ out, int rows)
{
    extern __shared__ char dyn[];
    float*  shB   = (float*) (dyn + OFF_B);     // [flat][state(32)]
    uint2*  sQ1b  = (uint2*) (dyn + OFF_Q1B);   // [f*32+lane]: bf16x4 of B[J_p][f]
    uint2*  sQ2b  = (uint2*) (dyn + OFF_Q2B);   // [f*32+lane]: bf16x4 of C_p*B[K2_p][f]
    short*  sFlat = (short*) (dyn + OFF_Q1B);   // ALIAS (consumed before Q1b built)
    short4* sTrip = (short4*)(dyn + OFF_TRIP);  // 4 rows x 684 packed triples
    float*  sA    = (float*) (dyn + OFF_A);
    float*  sI    = (float*) (dyn + OFF_I);
    float*  sRed  = (float*) (dyn + OFF_RED);
    const int tid = threadIdx.x;

    // ---- init ----
    for (int i = tid; i < NF*32; i += 128) shB[i] = ((i & 31) < 25) ? -1e30f : 0.0f;
    for (int i = tid; i < 625;   i += 128) sA[i] = -1e30f;
    __syncthreads();

    // ---- B logits ----
    if (tid < 29) {
        const int* d = c_adds[tid];
        addB(shB, ew, d[0], d[1], d[2], d[3], d[4], d[5], d[6]);
    }
    // ---- A logits ----
    if (tid == 32) {
        float w0=tw[0],w1=tw[1],w2=tw[2],w3=tw[3],w4=tw[4];
        float w5=tw[5],w6=tw[6],w7=tw[7],w8=tw[8],w9=tw[9];
        sA[0*25+0]=1.f-w0; sA[0*25+1]=w0;
        sA[1*25+2]=1.f;    sA[2*25+3]=1.f;
        sA[3*25+4]=w1;     sA[6*25+7]=w2;
        sA[4*25+5]=1.f;    sA[7*25+8]=1.f;
        sA[5*25+6]=1.f;    sA[8*25+9]=1.f;
        sA[3*25+14]=w3;    sA[6*25+17]=w4;   sA[9*25+20]=w5;
        sA[9*25+10]=1.f-w5;
        sA[14*25+15]=1.f;  sA[17*25+18]=1.f; sA[20*25+21]=1.f;
        sA[15*25+16]=1.f;  sA[18*25+19]=1.f; sA[21*25+22]=1.f;
        sA[16*25+4]=w6;    sA[19*25+7]=w7;   sA[22*25+10]=w8;
        sA[16*25+14]=1.f-w6; sA[19*25+17]=1.f-w7; sA[22*25+20]=1.f-w8;
        sA[3*25+7]=1.f - w9*w9;
        sA[3*25+10]=1.f - w9*w9*w9;
        sA[6*25+10]=1.f - w9*w9;
        sA[10*25+11]=1.f; sA[11*25+12]=1.f; sA[12*25+13]=1.f;
        sA[13*25+13]=1.f; sA[13*25+23]=1.f;
        sA[23*25+23]=1.f; sA[23*25+24]=1.f; sA[24*25+24]=1.f;
    }
    // ---- I softmax ----
    if (tid == 64) {
        float mx = -1e30f;
        for (int i = 0; i < 9; i++) mx = fmaxf(mx, iw[i]);
        float v[9], sum = 0.f;
        for (int i = 0; i < 9; i++) { v[i] = expf(iw[i]-mx); sum += v[i]; }
        for (int i = 0; i < 9; i++) sI[i] = v[i] / sum;
        for (int i = 9; i < 32; i++) sI[i] = 0.f;
    }

    // ---- per-warp: flat contexts (alias region) + packed triples ----
    const int lane = tid & 31;
    const int wq   = tid >> 5;
    const int row  = blockIdx.x * 4 + wq;
    short*  myFlat = sFlat + wq * TLEN;
    short4* myTrip = sTrip + wq * 684;
    const int* tok = tokens + (size_t)row * TLEN;
    int flat0 = 168, flat1 = 144;
    if (row < rows) {
        int c1 = 4, c2 = 4;
        for (int t0 = 0; t0 < TLEN; t0 += 32) {
            int tcv = tok[t0 + lane];
            int t1v = __shfl_up_sync(FULLMASK, tcv, 1);
            int t2v = __shfl_up_sync(FULLMASK, tcv, 2);
            if (lane == 0) { t1v = c1; t2v = c2; }
            if (lane == 1) { t2v = c1; }
            myFlat[t0 + lane] = (short)(t2v*36 + t1v*6 + tcv);
            c2 = __shfl_sync(FULLMASK, tcv, 30);
            c1 = __shfl_sync(FULLMASK, tcv, 31);
        }
        __syncwarp();
        for (int i = lane; i < NTRIP; i += 32) {
            int b = 2 + 3*i;
            myTrip[i] = make_short4(myFlat[b], myFlat[b+1], myFlat[b+2], 0);
        }
        flat0 = myFlat[0];     // save before Q1b overwrites the alias region
        flat1 = myFlat[1];
    }
    __syncthreads();

    // ---- A row softmax ----
    if (tid < 25) {
        float mx = -1e30f;
        for (int j = 0; j < 25; j++) mx = fmaxf(mx, sA[tid*25+j]);
        float s = 0.f;
        for (int j = 0; j < 25; j++) { float v = expf(sA[tid*25+j]-mx); sA[tid*25+j]=v; s+=v; }
        float inv = 1.f / s;
        for (int j = 0; j < 25; j++) sA[tid*25+j] *= inv;
    }
    // ---- B column softmax, 4-way parallel per state ----
    {
        const int s  = tid & 31;
        const int ch = tid >> 5;
        const int f0 = ch * 54, f1 = f0 + 54;
        float mx = -1e30f;
        for (int f = f0; f < f1; f++) mx = fmaxf(mx, shB[(f<<5)+s]);
        sRed[ch*32 + s] = mx;
        __syncthreads();
        mx = fmaxf(fmaxf(sRed[s], sRed[32+s]), fmaxf(sRed[64+s], sRed[96+s]));
        float sum = 0.f;
        for (int f = f0; f < f1; f++) {
            float v = __expf(shB[(f<<5)+s] - mx);
            shB[(f<<5)+s] = v; sum += v;
        }
        __syncthreads();
        sRed[ch*32 + s] = sum;
        __syncthreads();
        float tot = (sRed[s] + sRed[32+s]) + (sRed[64+s] + sRed[96+s]);
        float inv = 1.f / tot;
        for (int f = f0; f < f1; f++) shB[(f<<5)+s] *= inv;
    }
    __syncthreads();

    // ---- 3-step path table for lane j (<=4 paths; 23/24 intermediates pruned:
    //      B[23/24][f] = 0 on every reachable flat -> those paths are exactly 0) ----
    int   ps[4] = {0,0,0,0};
    int   j1[4] = {0,0,0,0};
    int   j2[4] = {0,0,0,0};
    float pcc[4] = {0.f,0.f,0.f,0.f};
    if (lane < 25) {
        int cnt = 0;
        for (int a2 = 0; a2 < c_pcnt[lane]; a2++) {
            int k2 = c_pred[lane][a2];
            if (k2 >= 23) continue;
            for (int a1 = 0; a1 < c_pcnt[k2]; a1++) {
                int k1 = c_pred[k2][a1];
                if (k1 >= 23) continue;
                for (int a0 = 0; a0 < c_pcnt[k1]; a0++) {
                    int s = c_pred[k1][a0];
                    ps[cnt] = s; j1[cnt] = k1; j2[cnt] = k2;
                    pcc[cnt] = sA[s*25+k1] * sA[k1*25+k2] * sA[k2*25+lane] * 8388608.0f; // 2^23
                    cnt++;
                }
            }
        }
    }
    const int S0 = ps[0], S1 = ps[1], S2 = ps[2], S3 = ps[3];

    // ---- build Q1b / Q2b tables (bf16x4, stride 32) ----
    {
        int ja0 = j1[0], ja1 = j1[1], ja2 = j1[2], ja3 = j1[3];
        int kb0 = j2[0], kb1 = j2[1], kb2 = j2[2], kb3 = j2[3];
        for (int f = wq * 54; f < wq * 54 + 54; f++) {
            int fo = f << 5;
            uint2 qa, qb;
            qa.x = bf16rn(shB[fo + ja0]) | (bf16rn(shB[fo + ja1]) << 16);
            qa.y = bf16rn(shB[fo + ja2]) | (bf16rn(shB[fo + ja3]) << 16);
            qb.x = bf16rn(pcc[0]*shB[fo + kb0]) | (bf16rn(pcc[1]*shB[fo + kb1]) << 16);
            qb.y = bf16rn(pcc[2]*shB[fo + kb2]) | (bf16rn(pcc[3]*shB[fo + kb3]) << 16);
            sQ1b[fo + lane] = qa;
            sQ2b[fo + lane] = qb;
        }
    }
    __syncthreads();

    // 1-step table (t=1)
    const int u0 = c_srcTab[lane*4+0], u1 = c_srcTab[lane*4+1];
    const int u2 = c_srcTab[lane*4+2], u3 = c_srcTab[lane*4+3];
    const int dg = c_deg[lane];
    float v0 = (lane < 25 && dg > 0) ? sA[u0*25 + lane] : 0.f;
    float v1 = (lane < 25 && dg > 1) ? sA[u1*25 + lane] : 0.f;
    float v2 = (lane < 25 && dg > 2) ? sA[u2*25 + lane] : 0.f;
    float v3 = (lane < 25 && dg > 3) ? sA[u3*25 + lane] : 0.f;

    if (row >= rows) return;

    // ---- t = 0 ----
    float a = sI[lane] * shB[(flat0 << 5) + lane];

    // ---- t = 1: single 1-step ----
    {
        float e = shB[(flat1 << 5) + lane];
        float x0 = __shfl_sync(FULLMASK, a, u0);
        float x1 = __shfl_sync(FULLMASK, a, u1);
        float x2 = __shfl_sync(FULLMASK, a, u2);
        float x3 = __shfl_sync(FULLMASK, a, u3);
        a = (fmaf(x0, v0, x1*v1) + fmaf(x2, v2, x3*v3)) * e;
    }
    int expsum = 0;
    float sc = 1.f; int pend = 0;

    // ---- head: triples 0,1 (measure at 0, apply at 1) ----
#define TRIPM(I, MODE)                                                        \
    {                                                                         \
        short4 tf = myTrip[(I)];                                              \
        uint2  qa = sQ1b[(((int)tf.x) << 5) + lane];                          \
        uint2  qb = sQ2b[(((int)tf.y) << 5) + lane];                          \
        float  e  = shB [(((int)tf.z) << 5) + lane];                          \
        float2 p01 = bfmul2(qa.x, qb.x);                                      \
        float2 p23 = bfmul2(qa.y, qb.y);                                      \
        float w0 = p01.x * e, w1 = p01.y * e, w2 = p23.x * e, w3 = p23.y * e; \
        float x0 = __shfl_sync(FULLMASK, a, S0);                              \
        float x1 = __shfl_sync(FULLMASK, a, S1);                              \
        float x2 = __shfl_sync(FULLMASK, a, S2);                              \
        float x3 = __shfl_sync(FULLMASK, a, S3);                              \
        a = fmaf(x1, w1, x0*w0) + fmaf(x3, w3, x2*w2);                        \
        if ((MODE) == 1) {                                                    \
            int m = __reduce_max_sync(FULLMASK, (__float_as_int(a) >> 23) & 255); \
            sc = __int_as_float((254 - m) << 23);                             \
            pend = m - 127;                                                   \
        }                                                                     \
        if ((MODE) == 2) { a *= sc; expsum += pend; }                         \
    }

    TRIPM(0, 1) TRIPM(1, 2)
#undef TRIPM

    // ---- main: 85 blocks of 8 triples (iters 2..681), trips in registers ----
#define STAGE(i)                                                              \
    {                                                                         \
        unsigned lo_ = (((i) >> 1) == 0) ? (((i)&1) ? T0.z : T0.x)            \
                     : (((i) >> 1) == 1) ? (((i)&1) ? T1.z : T1.x)            \
                     : (((i) >> 1) == 2) ? (((i)&1) ? T2.z : T2.x)            \
                     :                     (((i)&1) ? T3.z : T3.x);           \
        unsigned hi_ = (((i) >> 1) == 0) ? (((i)&1) ? T0.w : T0.y)            \
                     : (((i) >> 1) == 1) ? (((i)&1) ? T1.w : T1.y)            \
                     : (((i) >> 1) == 2) ? (((i)&1) ? T2.w : T2.y)            \
                     :                     (((i)&1) ? T3.w : T3.y);           \
        uint2  qa = sQ1b[(int)((lo_ & 0xffffu) << 5) + lane];                 \
        uint2  qb = sQ2b[(int)((lo_ >> 16)     << 5) + lane];                 \
        float  e  = shB [(int)(hi_             << 5) + lane];                 \
        float2 p01 = bfmul2(qa.x, qb.x);                                      \
        float2 p23 = bfmul2(qa.y, qb.y);                                      \
        W[(i)][0] = p01.x * e;                                                \
        W[(i)][1] = p01.y * e;                                                \
        W[(i)][2] = p23.x * e;                                                \
        W[(i)][3] = p23.y * e;                                                \
    }

    for (int ib = 2; ib <= 674; ib += 8) {
        const uint4* tp = (const uint4*)(myTrip + ib);   // ib even -> 16B aligned
        uint4 T0 = tp[0], T1 = tp[1], T2 = tp[2], T3 = tp[3];
        float W[8][4];
        STAGE(0) STAGE(1)
        #pragma unroll
        for (int i = 0; i < 8; i++) {
            if (i < 6) STAGE(i+2)
            float x0 = __shfl_sync(FULLMASK, a, S0);
            float x1 = __shfl_sync(FULLMASK, a, S1);
            float x2 = __shfl_sync(FULLMASK, a, S2);
            float x3 = __shfl_sync(FULLMASK, a, S3);
            a = fmaf(x1, W[i][1], x0*W[i][0]) + fmaf(x3, W[i][3], x2*W[i][2]);
            if (i == 5) {
                int m = __reduce_max_sync(FULLMASK, (__float_as_int(a) >> 23) & 255);
                sc = __int_as_float((254 - m) << 23);
                pend = m - 127;
            }
            if (i == 7) { a *= sc; expsum += pend; }
        }
    }
#undef STAGE

    // ---- final: ll = log(sum alpha) + (expsum - 23*682) * ln2 ----
    float s = a;
    #pragma unroll
    for (int o = 16; o; o >>= 1) s += __shfl_xor_sync(FULLMASK, s, o);
    if (lane == 0)
        out[row] = logf(s) + 0.6931471805599453f * (float)(expsum - 15686);
}

// ---------------- entry point ----------------
extern "C" void kernel_launch(void* const* d_in, const int* in_sizes, int n_in,
                              void* d_out, int out_size)
{
    const float* tw     = (const float*)d_in[0];
    const float* ew     = (const float*)d_in[1];
    const float* iw     = (const float*)d_in[2];
    const int*   tokens = (const int*)  d_in[3];
    float*       out    = (float*)d_out;

    int rows = in_sizes[3] / TLEN;

    cudaFuncSetAttribute(hmm_fused,
                         cudaFuncAttributeMaxDynamicSharedMemorySize,
                         SMEM_TOTAL);
    hmm_fused<<<(rows + 3) / 4, 128, SMEM_TOTAL>>>(tw, ew, iw, tokens, out, rows);
}